// round 10
// baseline (speedup 1.0000x reference)
#include <cuda_runtime.h>
#include <cstdint>

// Problem constants (fixed by the dataset)
#define BB 32
#define TT 2048
#define DD 256
#define D4 (DD / 4)            // 64 float4 lanes per row
#define NCHUNK 32
#define CHUNK (TT / NCHUNK)    // 64 rows per chunk
#define TPG 8                  // t-rows per thread
#define NGRP (CHUNK / TPG)     // 8 groups per block
#define SCAN_THREADS (D4 * NGRP)  // 512
#define NFLAG (BB * NCHUNK)    // 1024

// Scratch: exclusive prefix sums E[b][t][d], t in [0, TT]
__device__ float g_csum[(size_t)BB * (TT + 1) * DD];   // ~67 MB
// Per-chunk aggregate vectors (one float4 per lane)
__device__ float4 g_ctot[NFLAG * D4];
// Publish flags (zero-initialized; reset each replay by k_pairs block 0)
__device__ int g_flag[NFLAG];

// ---------------------------------------------------------------------------
// Single-pass scan with decoupled lookback (aggregate style).
// TPG=8 keeps the register file small enough for 2 blocks/SM (latency
// tolerance in the load phase). Input read with __ldcs (evict-first) so the
// 64 MB input doesn't evict the csum we want L2-resident for k_pairs.
// ---------------------------------------------------------------------------
__global__ __launch_bounds__(SCAN_THREADS, 2)
void k_scan(const float* __restrict__ x) {
    __shared__ float4 s_tot[NGRP][D4];   // per-group totals
    __shared__ float4 s_off[D4];         // chunk offset vector (from lookback)

    const int bid  = blockIdx.x;
    const int c    = bid & (NCHUNK - 1);
    const int b    = bid / NCHUNK;
    const int lane = threadIdx.x & (D4 - 1);
    const int grp  = threadIdx.x >> 6;

    const int t0 = c * CHUNK + grp * TPG;
    const float4* x4 = reinterpret_cast<const float4*>(x)
                       + ((size_t)b * TT + t0) * D4 + lane;

    // ---- Phase 1: load TPG rows into registers (streaming), per-thread total
    float4 v[TPG];
#pragma unroll
    for (int i = 0; i < TPG; i++) v[i] = __ldcs(&x4[(size_t)i * D4]);

    float4 tot = v[0];
#pragma unroll
    for (int i = 1; i < TPG; i++) {
        tot.x += v[i].x; tot.y += v[i].y; tot.z += v[i].z; tot.w += v[i].w;
    }
    s_tot[grp][lane] = tot;
    __syncthreads();

    // ---- Per-thread offset within the chunk (sum of previous groups)
    float4 goff = make_float4(0.f, 0.f, 0.f, 0.f);
    for (int g = 0; g < grp; g++) {
        float4 t2 = s_tot[g][lane];
        goff.x += t2.x; goff.y += t2.y; goff.z += t2.z; goff.w += t2.w;
    }

    // ---- Publish this chunk's aggregate (last group holds chunk total)
    if (grp == NGRP - 1) {
        float4 ct;
        ct.x = goff.x + tot.x; ct.y = goff.y + tot.y;
        ct.z = goff.z + tot.z; ct.w = goff.w + tot.w;
        g_ctot[bid * D4 + lane] = ct;
    }
    __syncthreads();
    if (threadIdx.x == (NGRP - 1) * D4) {
        __threadfence();                  // make aggregates device-visible
        atomicExch(&g_flag[bid], 1);      // release
    }

    // ---- Lookback: sum all predecessor aggregates (independent, no chain)
    float4 choff = make_float4(0.f, 0.f, 0.f, 0.f);
    if (c > 0) {
        if ((int)threadIdx.x < c) {
            volatile int* fl = g_flag + b * NCHUNK + threadIdx.x;
            while (*fl == 0) { __nanosleep(64); }
        }
        __syncthreads();
        __threadfence();                  // acquire before reading aggregates
        if (grp == 0) {
            float4 co = make_float4(0.f, 0.f, 0.f, 0.f);
            for (int j = 0; j < c; j++) {
                float4 t2 = g_ctot[(b * NCHUNK + j) * D4 + lane];
                co.x += t2.x; co.y += t2.y; co.z += t2.z; co.w += t2.w;
            }
            s_off[lane] = co;
        }
        __syncthreads();
        choff = s_off[lane];
    }

    // ---- Phase 2: write exclusive prefixes from registers (default policy:
    //      dirty lines allocate in L2 and stay resident for k_pairs)
    float4 run;
    run.x = choff.x + goff.x; run.y = choff.y + goff.y;
    run.z = choff.z + goff.z; run.w = choff.w + goff.w;

    float4* o4 = reinterpret_cast<float4*>(g_csum)
                 + ((size_t)b * (TT + 1) + t0) * D4 + lane;
#pragma unroll
    for (int i = 0; i < TPG; i++) {
        o4[(size_t)i * D4] = run;
        run.x += v[i].x; run.y += v[i].y; run.z += v[i].z; run.w += v[i].w;
    }
    if (c == NCHUNK - 1 && grp == NGRP - 1) {
        o4[(size_t)TPG * D4] = run;       // row TT (inclusive total)
    }
}

// ---------------------------------------------------------------------------
// K3: per-pair span means. 256 threads/block; each 64-thread group handles
// TWO pairs, issuing all 8 csum float4 loads before any arithmetic (MLP=8).
// Output stored with __stwt (write-through): no L2 allocation, so the 205 MB
// output stream cannot evict the L2-resident csum.
// Block 0 also resets the scan flags for the next graph replay.
// ---------------------------------------------------------------------------
__global__ __launch_bounds__(256)
void k_pairs(const int* __restrict__ p1_start,
             const int* __restrict__ p1_span,
             const int* __restrict__ p2_start,
             const int* __restrict__ p2_span,
             const int* __restrict__ pair_batch,
             float* __restrict__ out,
             int P) {
    if (blockIdx.x == 0) {
        for (int i = threadIdx.x; i < NFLAG; i += 256) g_flag[i] = 0;
    }

    const int grpi  = threadIdx.x >> 6;          // 0..3
    const int lane  = threadIdx.x & 63;
    const int pairA = (blockIdx.x * 4 + grpi) * 2;
    const int pairB = pairA + 1;
    if (pairA >= P) return;
    const bool hasB = (pairB < P);

    // ---- indices for both pairs
    const int bA  = pair_batch[pairA];
    const int a1A = p1_start[pairA];
    const int n1A = p1_span[pairA];
    const int a2A = p2_start[pairA];
    const int n2A = p2_span[pairA];

    const int bB  = hasB ? pair_batch[pairB] : 0;
    const int a1B = hasB ? p1_start[pairB] : 0;
    const int n1B = hasB ? p1_span[pairB] : 1;
    const int a2B = hasB ? p2_start[pairB] : 0;
    const int n2B = hasB ? p2_span[pairB] : 1;

    const float4* cs = reinterpret_cast<const float4*>(g_csum);
    const float4* baseA = cs + (size_t)bA * (TT + 1) * D4 + lane;
    const float4* baseB = cs + (size_t)bB * (TT + 1) * D4 + lane;

    // ---- issue all 8 loads back-to-back (MLP = 8)
    float4 hi1A = __ldg(&baseA[(size_t)(a1A + n1A) * D4]);
    float4 lo1A = __ldg(&baseA[(size_t)a1A * D4]);
    float4 hi2A = __ldg(&baseA[(size_t)(a2A + n2A) * D4]);
    float4 lo2A = __ldg(&baseA[(size_t)a2A * D4]);
    float4 hi1B = __ldg(&baseB[(size_t)(a1B + n1B) * D4]);
    float4 lo1B = __ldg(&baseB[(size_t)a1B * D4]);
    float4 hi2B = __ldg(&baseB[(size_t)(a2B + n2B) * D4]);
    float4 lo2B = __ldg(&baseB[(size_t)a2B * D4]);

    const float i1A = 1.0f / (float)n1A;
    const float i2A = 1.0f / (float)n2A;
    const float i1B = 1.0f / (float)n1B;
    const float i2B = 1.0f / (float)n2B;

    float4 r;
    float4* orowA = reinterpret_cast<float4*>(out) + (size_t)pairA * (2 * D4);

    r.x = (hi1A.x - lo1A.x) * i1A; r.y = (hi1A.y - lo1A.y) * i1A;
    r.z = (hi1A.z - lo1A.z) * i1A; r.w = (hi1A.w - lo1A.w) * i1A;
    __stwt(&orowA[lane], r);

    r.x = (hi2A.x - lo2A.x) * i2A; r.y = (hi2A.y - lo2A.y) * i2A;
    r.z = (hi2A.z - lo2A.z) * i2A; r.w = (hi2A.w - lo2A.w) * i2A;
    __stwt(&orowA[D4 + lane], r);

    if (hasB) {
        float4* orowB = reinterpret_cast<float4*>(out) + (size_t)pairB * (2 * D4);

        r.x = (hi1B.x - lo1B.x) * i1B; r.y = (hi1B.y - lo1B.y) * i1B;
        r.z = (hi1B.z - lo1B.z) * i1B; r.w = (hi1B.w - lo1B.w) * i1B;
        __stwt(&orowB[lane], r);

        r.x = (hi2B.x - lo2B.x) * i2B; r.y = (hi2B.y - lo2B.y) * i2B;
        r.z = (hi2B.z - lo2B.z) * i2B; r.w = (hi2B.w - lo2B.w) * i2B;
        __stwt(&orowB[D4 + lane], r);
    }
}

// ---------------------------------------------------------------------------
extern "C" void kernel_launch(void* const* d_in, const int* in_sizes, int n_in,
                              void* d_out, int out_size) {
    const float* token_embs = (const float*)d_in[0];
    const int* p1_start   = (const int*)d_in[1];
    const int* p1_span    = (const int*)d_in[2];
    const int* p2_start   = (const int*)d_in[3];
    const int* p2_span    = (const int*)d_in[4];
    const int* pair_batch = (const int*)d_in[5];
    float* out = (float*)d_out;

    const int P = in_sizes[1];

    k_scan<<<BB * NCHUNK, SCAN_THREADS>>>(token_embs);

    const int pairs_per_block = 8;   // 4 groups x 2 pairs
    const int gridP = (P + pairs_per_block - 1) / pairs_per_block;
    k_pairs<<<gridP, 256>>>(p1_start, p1_span, p2_start, p2_span, pair_batch,
                            out, P);
}